// round 11
// baseline (speedup 1.0000x reference)
#include <cuda_runtime.h>

// DCT band decomposition: x[16,3,512,512] f32 -> (low, mid, high) concatenated.
// One thread per 8x8 block. Butterfly forward DCT. Stage-1 of the masked
// inverse computed ONCE with nested k-prefixes per column (low = k<K0,
// low+mid = k<K1), sharing all FMAs; mid = P1row - lowrow in row space;
// high = (x - P1row)*s2 with x re-read from L1. Constants fold to FFMA imm.

namespace {
constexpr int H = 512, W = 512;
constexpr int NPIX = 16 * 3 * H * W;             // 12582912
constexpr int NBLK = 16 * 3 * (H / 8) * (W / 8); // 196608
constexpr int TPB  = 128;
}

#define A4f 0.3535533905932738f
#define C1f 0.4903926402016152f
#define C2f 0.4619397662556434f
#define C3f 0.4157348061512726f
#define C5f 0.2777851165098011f
#define C6f 0.1913417161825449f
#define C7f 0.0975451610080641f

__host__ __device__ constexpr float Dv(int k, int t) {
    constexpr float m[8][8] = {
        { A4f,  A4f,  A4f,  A4f,  A4f,  A4f,  A4f,  A4f},
        { C1f,  C3f,  C5f,  C7f, -C7f, -C5f, -C3f, -C1f},
        { C2f,  C6f, -C6f, -C2f, -C2f, -C6f,  C6f,  C2f},
        { C3f, -C7f, -C1f, -C5f,  C5f,  C1f,  C7f, -C3f},
        { A4f, -A4f, -A4f,  A4f,  A4f, -A4f, -A4f,  A4f},
        { C5f, -C1f,  C7f,  C3f, -C3f, -C7f,  C1f, -C5f},
        { C6f, -C2f,  C2f, -C6f, -C6f,  C2f, -C2f,  C6f},
        { C7f, -C5f,  C3f, -C1f,  C1f, -C3f,  C5f, -C7f}
    };
    return m[k][t];
}

// Zigzag bands as nested k-prefixes per column l:
//   low      : k < K0(l)           (low: k+l <= 5)
//   low+mid  : k < K1(l)           (mid: 6 <= k+l <= 8, excluding (1,7))
// K1(7)=1 because (1,7) belongs to HIGH (zigzag index 42).
__host__ __device__ constexpr int K0v(int l) { return (l <= 5) ? (6 - l) : 0; }
__host__ __device__ constexpr int K1v(int l) {
    return (l == 0) ? 8 : ((l == 7) ? 1 : (9 - l));
}

// Fast 8-point DCT-II (orthonormal) in place.
__device__ __forceinline__ void dct8(float x[8]) {
    const float e0 = x[0] + x[7], e1 = x[1] + x[6], e2 = x[2] + x[5], e3 = x[3] + x[4];
    const float o0 = x[0] - x[7], o1 = x[1] - x[6], o2 = x[2] - x[5], o3 = x[3] - x[4];
    const float f0 = e0 + e3, f1 = e1 + e2;
    const float g0 = e0 - e3, g1 = e1 - e2;
    x[0] = A4f * (f0 + f1);
    x[4] = A4f * (f0 - f1);
    x[2] = fmaf(C2f, g0,  C6f * g1);
    x[6] = fmaf(C6f, g0, -C2f * g1);
    x[1] = fmaf(C1f, o0, fmaf( C3f, o1, fmaf( C5f, o2,  C7f * o3)));
    x[3] = fmaf(C3f, o0, fmaf(-C7f, o1, fmaf(-C1f, o2, -C5f * o3)));
    x[5] = fmaf(C5f, o0, fmaf(-C1f, o1, fmaf( C7f, o2,  C3f * o3)));
    x[7] = fmaf(C7f, o0, fmaf(-C5f, o1, fmaf( C3f, o2, -C1f * o3)));
}

// Stage 2 + stores for one spatial row r:
//  lrow = yL * D (low, cols l<6 active), prow = yP * D (all cols),
//  low = lrow*s0, mid = (prow-lrow)*s1, high = (x - prow)*s2.
__device__ __forceinline__ void rows_emit(
    const float yL[8], const float yP[8],
    const float* __restrict__ xrow,
    float s0, float s1, float s2,
    float* __restrict__ dlow, float* __restrict__ dmid,
    float* __restrict__ dhigh)
{
    // x reload: L1 hit (same addresses as initial block load, same launch)
    const float4 xa = __ldg(reinterpret_cast<const float4*>(xrow));
    const float4 xb = __ldg(reinterpret_cast<const float4*>(xrow + 4));

    float lr[8], pr[8];
#pragma unroll
    for (int n = 0; n < 4; n++) {
        float LE = 0.0f, LO = 0.0f, PE = 0.0f, PO = 0.0f;
#pragma unroll
        for (int l = 0; l < 8; l += 2) {
            if (l < 6) LE = fmaf(yL[l], Dv(l, n), LE);
            PE = fmaf(yP[l], Dv(l, n), PE);
        }
#pragma unroll
        for (int l = 1; l < 8; l += 2) {
            if (l < 6) LO = fmaf(yL[l], Dv(l, n), LO);
            PO = fmaf(yP[l], Dv(l, n), PO);
        }
        lr[n]     = LE + LO;  lr[7 - n] = LE - LO;
        pr[n]     = PE + PO;  pr[7 - n] = PE - PO;
    }

    __stcs(reinterpret_cast<float4*>(dlow),
           make_float4(lr[0] * s0, lr[1] * s0, lr[2] * s0, lr[3] * s0));
    __stcs(reinterpret_cast<float4*>(dlow + 4),
           make_float4(lr[4] * s0, lr[5] * s0, lr[6] * s0, lr[7] * s0));

    __stcs(reinterpret_cast<float4*>(dmid),
           make_float4((pr[0] - lr[0]) * s1, (pr[1] - lr[1]) * s1,
                       (pr[2] - lr[2]) * s1, (pr[3] - lr[3]) * s1));
    __stcs(reinterpret_cast<float4*>(dmid + 4),
           make_float4((pr[4] - lr[4]) * s1, (pr[5] - lr[5]) * s1,
                       (pr[6] - lr[6]) * s1, (pr[7] - lr[7]) * s1));

    __stcs(reinterpret_cast<float4*>(dhigh),
           make_float4((xa.x - pr[0]) * s2, (xa.y - pr[1]) * s2,
                       (xa.z - pr[2]) * s2, (xa.w - pr[3]) * s2));
    __stcs(reinterpret_cast<float4*>(dhigh + 4),
           make_float4((xb.x - pr[4]) * s2, (xb.y - pr[5]) * s2,
                       (xb.z - pr[6]) * s2, (xb.w - pr[7]) * s2));
}

__global__ void __launch_bounds__(TPB, 6)
dct_decomp_kernel(const float* __restrict__ x,
                  const float* __restrict__ band_scale,
                  float* __restrict__ out)
{
    const int tid = blockIdx.x * TPB + threadIdx.x;   // grid sized exactly
    const int bw = tid & 63;          // block col (W/8 = 64)
    const int bh = (tid >> 6) & 63;   // block row
    const int bc = tid >> 12;         // fused batch*chan

    const size_t base = ((size_t)bc * H + (size_t)bh * 8) * W + (size_t)bw * 8;
    const float* src = x + base;

    const float s0 = __ldg(band_scale + 0);
    const float s1 = __ldg(band_scale + 1);
    const float s2 = __ldg(band_scale + 2);

    // ---- Load 8x8 block (16 LDG.128, front-batched; input L2-resident) ----
    float C[8][8];
#pragma unroll
    for (int r = 0; r < 8; r++) {
        float4 a = __ldg(reinterpret_cast<const float4*>(src + (size_t)r * W));
        float4 b = __ldg(reinterpret_cast<const float4*>(src + (size_t)r * W + 4));
        C[r][0] = a.x; C[r][1] = a.y; C[r][2] = a.z; C[r][3] = a.w;
        C[r][4] = b.x; C[r][5] = b.y; C[r][6] = b.z; C[r][7] = b.w;
    }

    // ---- Forward 2D DCT in place: columns then rows ----
    // (C[k][l] with k >= K1(l) is never consumed -> ptxas DCEs those chains.)
#pragma unroll
    for (int t = 0; t < 8; t++) {
        float col[8];
#pragma unroll
        for (int m = 0; m < 8; m++) col[m] = C[m][t];
        dct8(col);
#pragma unroll
        for (int k = 0; k < 8; k++) C[k][t] = col[k];
    }
#pragma unroll
    for (int k = 0; k < 8; k++)
        dct8(C[k]);

    float* dlow  = out + base;
    float* dmid  = out + (size_t)NPIX + base;
    float* dhigh = out + 2 * (size_t)NPIX + base;

    // ---- Stage 1 with nested prefixes, row pairs (m, 7-m) via k-parity ----
#pragma unroll
    for (int m = 0; m < 4; m++) {
        float yLA[8], yLB[8], yPA[8], yPB[8];
#pragma unroll
        for (int l = 0; l < 8; l++) {
            float se = 0.0f, so = 0.0f;
#pragma unroll
            for (int k = 0; k < 8; k += 2)
                if (k < K0v(l)) se = fmaf(C[k][l], Dv(k, m), se);
#pragma unroll
            for (int k = 1; k < 8; k += 2)
                if (k < K0v(l)) so = fmaf(C[k][l], Dv(k, m), so);
            const float seL = se, soL = so;   // low snapshot
#pragma unroll
            for (int k = 0; k < 8; k += 2)
                if (k >= K0v(l) && k < K1v(l)) se = fmaf(C[k][l], Dv(k, m), se);
#pragma unroll
            for (int k = 1; k < 8; k += 2)
                if (k >= K0v(l) && k < K1v(l)) so = fmaf(C[k][l], Dv(k, m), so);
            yLA[l] = seL + soL;  yLB[l] = seL - soL;   // low, rows m / 7-m
            yPA[l] = se + so;    yPB[l] = se - so;     // low+mid
        }
        rows_emit(yLA, yPA, src + (size_t)m * W, s0, s1, s2,
                  dlow + (size_t)m * W, dmid + (size_t)m * W,
                  dhigh + (size_t)m * W);
        rows_emit(yLB, yPB, src + (size_t)(7 - m) * W, s0, s1, s2,
                  dlow + (size_t)(7 - m) * W, dmid + (size_t)(7 - m) * W,
                  dhigh + (size_t)(7 - m) * W);
    }
}

extern "C" void kernel_launch(void* const* d_in, const int* in_sizes, int n_in,
                              void* d_out, int out_size)
{
    const float* x  = (const float*)d_in[0];
    const float* bs = (const float*)d_in[1];
    float* out = (float*)d_out;

    const int grid = NBLK / TPB;   // 1536
    dct_decomp_kernel<<<grid, TPB>>>(x, bs, out);
}

// round 12
// speedup vs baseline: 1.7189x; 1.7189x over previous
#include <cuda_runtime.h>

// DCT band decomposition: x[16,3,512,512] f32 -> (low, mid, high) concatenated.
// One thread per 8x8 block. Butterfly forward DCT; band IDCTs exploit
// m/(7-m) and n/(7-n) cosine symmetry; DCT constants fold to FFMA immediates.
// NEW: Blackwell 256-bit global loads/stores (v8.f32) -- each lane moves its
// full 32B row chunk in one instruction: fully-written sectors, half the
// L1tex store wavefronts, 24 fewer STG + 8 fewer LDG per thread.

namespace {
constexpr int H = 512, W = 512;
constexpr int NPIX = 16 * 3 * H * W;             // 12582912
constexpr int NBLK = 16 * 3 * (H / 8) * (W / 8); // 196608
constexpr int TPB  = 128;
}

#define A4f 0.3535533905932738f
#define C1f 0.4903926402016152f
#define C2f 0.4619397662556434f
#define C3f 0.4157348061512726f
#define C5f 0.2777851165098011f
#define C6f 0.1913417161825449f
#define C7f 0.0975451610080641f

__host__ __device__ constexpr float Dv(int k, int t) {
    constexpr float m[8][8] = {
        { A4f,  A4f,  A4f,  A4f,  A4f,  A4f,  A4f,  A4f},
        { C1f,  C3f,  C5f,  C7f, -C7f, -C5f, -C3f, -C1f},
        { C2f,  C6f, -C6f, -C2f, -C2f, -C6f,  C6f,  C2f},
        { C3f, -C7f, -C1f, -C5f,  C5f,  C1f,  C7f, -C3f},
        { A4f, -A4f, -A4f,  A4f,  A4f, -A4f, -A4f,  A4f},
        { C5f, -C1f,  C7f,  C3f, -C3f, -C7f,  C1f, -C5f},
        { C6f, -C2f,  C2f, -C6f, -C6f,  C2f, -C2f,  C6f},
        { C7f, -C5f,  C3f, -C1f,  C1f, -C3f,  C5f, -C7f}
    };
    return m[k][t];
}

// Zigzag bands: low = zz<21 <=> k+l<=5 ; mid = 21<=zz<42 <=> 6<=k+l<=8 \ (1,7)
__host__ __device__ constexpr bool in_band(int band, int k, int l) {
    const int s = k + l;
    const bool low = (s <= 5);
    const bool mid = (s >= 6 && s <= 8) && !(k == 1 && l == 7);
    if (band == 0) return low;
    if (band == 1) return mid;
    return !low && !mid;
}
__host__ __device__ constexpr bool col_active(int band, int l) {
    bool a = false;
    for (int k = 0; k < 8; k++) if (in_band(band, k, l)) a = true;
    return a;
}

// ---- 256-bit global memory ops (sm_100a/sm_103a) ----
__device__ __forceinline__ void ldg256(const float* p, float v[8]) {
    asm("ld.global.nc.v8.f32 {%0,%1,%2,%3,%4,%5,%6,%7}, [%8];"
        : "=f"(v[0]), "=f"(v[1]), "=f"(v[2]), "=f"(v[3]),
          "=f"(v[4]), "=f"(v[5]), "=f"(v[6]), "=f"(v[7])
        : "l"(p));
}
__device__ __forceinline__ void stg256_cs(float* p, const float v[8]) {
    asm volatile("st.global.cs.v8.f32 [%0], {%1,%2,%3,%4,%5,%6,%7,%8};"
                 :: "l"(p),
                    "f"(v[0]), "f"(v[1]), "f"(v[2]), "f"(v[3]),
                    "f"(v[4]), "f"(v[5]), "f"(v[6]), "f"(v[7])
                 : "memory");
}

// Fast 8-point DCT-II (orthonormal) in place.
__device__ __forceinline__ void dct8(float x[8]) {
    const float e0 = x[0] + x[7], e1 = x[1] + x[6], e2 = x[2] + x[5], e3 = x[3] + x[4];
    const float o0 = x[0] - x[7], o1 = x[1] - x[6], o2 = x[2] - x[5], o3 = x[3] - x[4];
    const float f0 = e0 + e3, f1 = e1 + e2;
    const float g0 = e0 - e3, g1 = e1 - e2;
    x[0] = A4f * (f0 + f1);
    x[4] = A4f * (f0 - f1);
    x[2] = fmaf(C2f, g0,  C6f * g1);
    x[6] = fmaf(C6f, g0, -C2f * g1);
    x[1] = fmaf(C1f, o0, fmaf( C3f, o1, fmaf( C5f, o2,  C7f * o3)));
    x[3] = fmaf(C3f, o0, fmaf(-C7f, o1, fmaf(-C1f, o2, -C5f * o3)));
    x[5] = fmaf(C5f, o0, fmaf(-C1f, o1, fmaf( C7f, o2,  C3f * o3)));
    x[7] = fmaf(C7f, o0, fmaf(-C5f, o1, fmaf( C3f, o2, -C1f * o3)));
}

// Stage 2 of masked IDCT: o[n] = sum_l y[l]*Dv(l,n) with n/(7-n) symmetry.
template <int BAND>
__device__ __forceinline__ void idct_row_store(const float y[8],
                                               float* __restrict__ dst)
{
    float o[8];
#pragma unroll
    for (int n = 0; n < 4; n++) {
        float E = 0.0f, O = 0.0f;
#pragma unroll
        for (int l = 0; l < 8; l += 2)
            if (col_active(BAND, l)) E = fmaf(y[l], Dv(l, n), E);
#pragma unroll
        for (int l = 1; l < 8; l += 2)
            if (col_active(BAND, l)) O = fmaf(y[l], Dv(l, n), O);
        o[n]     = E + O;
        o[7 - n] = E - O;
    }
    stg256_cs(dst, o);
}

// Masked inverse DCT of one band, row pairs (m, 7-m):
// Dv(k,7-m) = (-1)^k Dv(k,m), so stage-1 even/odd-k partial sums are shared.
template <int BAND>
__device__ __forceinline__ void band_idct(const float C[8][8], float scale,
                                          float* __restrict__ dst)
{
#pragma unroll
    for (int m = 0; m < 4; m++) {
        float yA[8], yB[8];
#pragma unroll
        for (int l = 0; l < 8; l++) {
            if (col_active(BAND, l)) {
                float se = 0.0f, so = 0.0f;
#pragma unroll
                for (int k = 0; k < 8; k += 2)
                    if (in_band(BAND, k, l)) se = fmaf(C[k][l], Dv(k, m), se);
#pragma unroll
                for (int k = 1; k < 8; k += 2)
                    if (in_band(BAND, k, l)) so = fmaf(C[k][l], Dv(k, m), so);
                yA[l] = (se + so) * scale;   // row m
                yB[l] = (se - so) * scale;   // row 7-m
            } else {
                yA[l] = 0.0f; yB[l] = 0.0f;
            }
        }
        idct_row_store<BAND>(yA, dst + (size_t)m * W);
        idct_row_store<BAND>(yB, dst + (size_t)(7 - m) * W);
    }
}

__global__ void __launch_bounds__(TPB, 6)
dct_decomp_kernel(const float* __restrict__ x,
                  const float* __restrict__ band_scale,
                  float* __restrict__ out)
{
    const int tid = blockIdx.x * TPB + threadIdx.x;   // grid sized exactly
    const int bw = tid & 63;          // block col (W/8 = 64)
    const int bh = (tid >> 6) & 63;   // block row
    const int bc = tid >> 12;         // fused batch*chan

    const size_t base = ((size_t)bc * H + (size_t)bh * 8) * W + (size_t)bw * 8;
    const float* src = x + base;

    const float s0 = __ldg(band_scale + 0);
    const float s1 = __ldg(band_scale + 1);
    const float s2 = __ldg(band_scale + 2);

    // ---- Load 8x8 block: 8 independent 256-bit loads, front-batched ----
    float C[8][8];
#pragma unroll
    for (int r = 0; r < 8; r++)
        ldg256(src + (size_t)r * W, C[r]);

    // ---- Forward 2D DCT in place: columns then rows, butterflied ----
#pragma unroll
    for (int t = 0; t < 8; t++) {
        float col[8];
#pragma unroll
        for (int m = 0; m < 8; m++) col[m] = C[m][t];
        dct8(col);
#pragma unroll
        for (int k = 0; k < 8; k++) C[k][t] = col[k];
    }
#pragma unroll
    for (int k = 0; k < 8; k++)
        dct8(C[k]);

    // ---- Three masked inverse DCTs ----
    band_idct<0>(C, s0, out + base);
    band_idct<1>(C, s1, out + (size_t)NPIX + base);
    band_idct<2>(C, s2, out + 2 * (size_t)NPIX + base);
}

extern "C" void kernel_launch(void* const* d_in, const int* in_sizes, int n_in,
                              void* d_out, int out_size)
{
    const float* x  = (const float*)d_in[0];
    const float* bs = (const float*)d_in[1];
    float* out = (float*)d_out;

    const int grid = NBLK / TPB;   // 1536
    dct_decomp_kernel<<<grid, TPB>>>(x, bs, out);
}